// round 3
// baseline (speedup 1.0000x reference)
#include <cuda_runtime.h>
#include <cuda_bf16.h>
#include <cstdint>

// ---------------------------------------------------------------------------
// DeepTopK sparse autoencoder forward + loss, fp32 throughout.
//   x:[2048,1024]  W_enc1:[1024,4096] W_enc2:[4096,16384]
//   W_dec2:[16384,4096] W_dec1:[4096,1024]
// Outputs: recon [2048*1024] then loss, l2_loss, aux_loss.
// ---------------------------------------------------------------------------

#define NTOK   2048
#define DM     1024
#define DMID   4096
#define DFEAT  16384
#define KMID   128
#define KFEAT  64
#define KAUXM  256
#define KAUXF  512
#define KCAP   512

// ------------------------- scratch (static device) -------------------------
__device__ float g_pre0[NTOK * DMID];     // 32MB
__device__ float g_pre1[(size_t)NTOK * DFEAT];    // 128MB
__device__ float g_pre2[NTOK * DMID];     // 32MB
__device__ float g_tfeat[(size_t)NTOK * DFEAT];   // 128MB
__device__ float g_tmid[NTOK * DMID];     // 32MB
__device__ float g_resid[NTOK * DM];      // 8MB

__device__ float g_valA[NTOK * KCAP];
__device__ int   g_idxA[NTOK * KCAP];
__device__ int   g_cntA[NTOK];
__device__ float g_valB[NTOK * KCAP];
__device__ int   g_idxB[NTOK * KCAP];
__device__ int   g_cntB[NTOK];

__device__ int g_act0[DMID];
__device__ int g_act1[DFEAT];
__device__ int g_act2[DMID];
__device__ int g_dead0[DMID];
__device__ int g_dead1[DFEAT];
__device__ int g_dead2[DMID];
__device__ int g_anydead[3];

__device__ float g_part[4 * NTOK];  // 0: l2, 1..3: aux terms

// ------------------------------ init ---------------------------------------
__global__ void init_kernel() {
    int i = blockIdx.x * blockDim.x + threadIdx.x;
    int total = DMID + DFEAT + DMID + 3;
    if (i >= total) return;
    if (i < DMID)               g_act0[i] = 0;
    else if (i < DMID + DFEAT)  g_act1[i - DMID] = 0;
    else if (i < DMID + DFEAT + DMID) g_act2[i - DMID - DFEAT] = 0;
    else                        g_anydead[i - DMID - DFEAT - DMID] = 0;
}

// ------------------------- dense SGEMM (layer 1) ----------------------------
// C[M,N] = relu(A[M,K] @ B[K,N] + bias[N]); M=2048,K=1024,N=4096
__global__ __launch_bounds__(256) void sgemm_bias_relu(
    const float* __restrict__ A, const float* __restrict__ B,
    const float* __restrict__ bias, float* __restrict__ C,
    int M, int N, int K)
{
    const int BM = 128, BN = 128, BK = 8, TM = 8, TN = 8;
    __shared__ float As[BK * BM];
    __shared__ float Bs[BK * BN];
    int tid = threadIdx.x;
    int tileN = blockIdx.x, tileM = blockIdx.y;
    const float* Ab = A + (size_t)tileM * BM * K;
    const float* Bb = B + (size_t)tileN * BN;
    float* Cb = C + (size_t)tileM * BM * N + (size_t)tileN * BN;

    int innerRowA = tid / 2;         // 0..127
    int innerColA = (tid % 2) * 4;   // 0 or 4
    int innerRowB = tid / 32;        // 0..7
    int innerColB = (tid % 32) * 4;  // 0..124
    int threadRow = tid / 16;        // 0..15
    int threadCol = tid % 16;        // 0..15

    float acc[TM][TN];
#pragma unroll
    for (int i = 0; i < TM; i++)
#pragma unroll
        for (int j = 0; j < TN; j++) acc[i][j] = 0.f;
    float regM[TM], regN[TN];

    for (int k0 = 0; k0 < K; k0 += BK) {
        float4 a = *reinterpret_cast<const float4*>(Ab + (size_t)innerRowA * K + k0 + innerColA);
        As[(innerColA + 0) * BM + innerRowA] = a.x;
        As[(innerColA + 1) * BM + innerRowA] = a.y;
        As[(innerColA + 2) * BM + innerRowA] = a.z;
        As[(innerColA + 3) * BM + innerRowA] = a.w;
        *reinterpret_cast<float4*>(&Bs[innerRowB * BN + innerColB]) =
            *reinterpret_cast<const float4*>(Bb + (size_t)(k0 + innerRowB) * N + innerColB);
        __syncthreads();
#pragma unroll
        for (int k = 0; k < BK; k++) {
#pragma unroll
            for (int i = 0; i < TM; i++) regM[i] = As[k * BM + threadRow * TM + i];
#pragma unroll
            for (int j = 0; j < TN; j++) regN[j] = Bs[k * BN + threadCol * TN + j];
#pragma unroll
            for (int i = 0; i < TM; i++)
#pragma unroll
                for (int j = 0; j < TN; j++)
                    acc[i][j] = fmaf(regM[i], regN[j], acc[i][j]);
        }
        __syncthreads();
    }
#pragma unroll
    for (int i = 0; i < TM; i++) {
        int row = threadRow * TM + i;
#pragma unroll
        for (int j = 0; j < TN; j++) {
            int col = threadCol * TN + j;
            float v = acc[i][j] + bias[tileN * BN + col];
            v = fmaxf(v, 0.f);
            Cb[(size_t)row * N + col] = v;
        }
    }
}

// ----------------------------- TopK (radix select) --------------------------
// One block per row. Keys are float bits | 0x80000000 (inputs are relu'd, >=0);
// in dead-mask mode, live features map to key 0 (acts as -inf).
// Emission is deterministic (index order: strict-greater first, then ties).
__global__ __launch_bounds__(256) void topk_kernel(
    const float* __restrict__ in, int D, int k,
    const int* __restrict__ dead,
    int* __restrict__ out_idx, float* __restrict__ out_val,
    int* __restrict__ out_cnt, int* __restrict__ act)
{
    extern __shared__ uint32_t skey[];
    __shared__ unsigned int hist[256];
    __shared__ int sg[256], st[256];
    __shared__ uint32_t s_uT;
    __shared__ int s_remk, s_totg, s_tott;
    const int NT = 256;
    int tid = threadIdx.x;
    const float* row = in + (size_t)blockIdx.x * D;

    for (int i = tid; i < D; i += NT) {
        uint32_t u;
        if (dead && !dead[i]) u = 0u;
        else u = __float_as_uint(row[i]) | 0x80000000u;
        skey[i] = u;
    }
    __syncthreads();

    uint32_t prefix = 0, himask = 0;
    int remk = k;
    for (int pass = 0; pass < 4; ++pass) {
        int shift = 24 - 8 * pass;
        hist[tid] = 0u;
        __syncthreads();
        for (int i = tid; i < D; i += NT) {
            uint32_t u = skey[i];
            if ((u & himask) == prefix) atomicAdd(&hist[(u >> shift) & 255u], 1u);
        }
        __syncthreads();
        if (tid == 0) {
            int cum = 0, b = 0;
            for (int bb = 255; bb >= 0; --bb) {
                int h = (int)hist[bb];
                if (cum + h >= remk) { b = bb; break; }
                cum += h;
            }
            s_uT = prefix | ((uint32_t)b << shift);
            s_remk = remk - cum;
        }
        __syncthreads();
        prefix = s_uT;
        remk = s_remk;
        himask |= (0xFFu << shift);
        __syncthreads();
    }
    uint32_t uT = prefix;

    // deterministic chunked emission
    int C = D / NT;
    int base = tid * C;
    int gc = 0, tc = 0;
    for (int i = 0; i < C; i++) {
        uint32_t u = skey[base + i];
        if (u > uT) gc++;
        else if (u == uT && u != 0u) tc++;
    }
    sg[tid] = gc; st[tid] = tc;
    __syncthreads();
    if (tid == 0) {
        int ag = 0, at = 0;
        for (int t = 0; t < NT; t++) {
            int g = sg[t]; sg[t] = ag; ag += g;
            int tt = st[t]; st[t] = at; at += tt;
        }
        s_totg = ag; s_tott = at;
    }
    __syncthreads();
    int gpos = sg[tid], tpos = st[tid];
    int Kg = s_totg;
    size_t ob = (size_t)blockIdx.x * KCAP;
    for (int i = 0; i < C; i++) {
        uint32_t u = skey[base + i];
        if (u > uT) {
            float v = __uint_as_float(u & 0x7FFFFFFFu);
            out_idx[ob + gpos] = base + i;
            out_val[ob + gpos] = v;
            if (act && v > 0.f) act[base + i] = 1;
            gpos++;
        } else if (u == uT && u != 0u) {
            if (tpos < remk) {
                float v = __uint_as_float(u & 0x7FFFFFFFu);
                int s = Kg + tpos;
                out_idx[ob + s] = base + i;
                out_val[ob + s] = v;
                if (act && v > 0.f) act[base + i] = 1;
            }
            tpos++;
        }
    }
    if (tid == 0) {
        int ties = s_tott < remk ? s_tott : remk;
        out_cnt[blockIdx.x] = Kg + ties;
    }
}

// -------------------------- gather-SpMM ------------------------------------
// out[tok, :] = (relu?)(sum_j val_j * W[idx_j, :] + bias)
// grid = (NTOK, Dout/(256*CPT)); blockIdx.x fastest => same column chunk for
// all tokens runs consecutively => W chunk stays in L2.
template <int CPT>
__global__ __launch_bounds__(256) void spgemm_kernel(
    const float* __restrict__ vals, const int* __restrict__ idxs,
    const int* __restrict__ cnts,
    const float* __restrict__ W, const float* __restrict__ bias,
    float* __restrict__ out, int Dout, int do_relu)
{
    __shared__ float sv[KCAP];
    __shared__ int si[KCAP];
    int tok = blockIdx.x, tid = threadIdx.x;
    int Keff = cnts[tok];
    for (int i = tid; i < Keff; i += 256) {
        sv[i] = vals[(size_t)tok * KCAP + i];
        si[i] = idxs[(size_t)tok * KCAP + i];
    }
    __syncthreads();
    int col0 = blockIdx.y * (256 * CPT) + tid;
    float acc[CPT];
#pragma unroll
    for (int c = 0; c < CPT; c++) acc[c] = bias[col0 + c * 256];
    for (int j = 0; j < Keff; j++) {
        float v = sv[j];
        const float* w = W + (size_t)si[j] * Dout + col0;
#pragma unroll
        for (int c = 0; c < CPT; c++)
            acc[c] = fmaf(v, __ldg(w + c * 256), acc[c]);
    }
    float* o = out + (size_t)tok * Dout + col0;
#pragma unroll
    for (int c = 0; c < CPT; c++) {
        float r = acc[c];
        if (do_relu) r = fmaxf(r, 0.f);
        o[c * 256] = r;
    }
}

// ----------------- final-layer SpMM + squared-error partials ----------------
// Dout = 1024, CPT = 4.  recon mode (x != nullptr): writes recon to recon_out,
// residual (x - recon) to resid_out, partial sum of (recon-x)^2 to part[tok].
// aux mode: partial sum of (h - resid_in)^2 to part[tok].
__global__ __launch_bounds__(256) void spgemm_final_kernel(
    const float* __restrict__ vals, const int* __restrict__ idxs,
    const int* __restrict__ cnts,
    const float* __restrict__ W, const float* __restrict__ bias,
    const float* __restrict__ x, float* __restrict__ recon_out,
    float* __restrict__ resid_out, const float* __restrict__ resid_in,
    float* __restrict__ part)
{
    const int CPT = 4;
    __shared__ float sv[KCAP];
    __shared__ int si[KCAP];
    __shared__ float sred[256];
    int tok = blockIdx.x, tid = threadIdx.x;
    int Keff = cnts[tok];
    for (int i = tid; i < Keff; i += 256) {
        sv[i] = vals[(size_t)tok * KCAP + i];
        si[i] = idxs[(size_t)tok * KCAP + i];
    }
    __syncthreads();
    int col0 = tid;
    float acc[CPT];
#pragma unroll
    for (int c = 0; c < CPT; c++) acc[c] = bias[col0 + c * 256];
    for (int j = 0; j < Keff; j++) {
        float v = sv[j];
        const float* w = W + (size_t)si[j] * DM + col0;
#pragma unroll
        for (int c = 0; c < CPT; c++)
            acc[c] = fmaf(v, __ldg(w + c * 256), acc[c]);
    }
    size_t ob = (size_t)tok * DM;
    float local = 0.f;
#pragma unroll
    for (int c = 0; c < CPT; c++) {
        int col = col0 + c * 256;
        float r = acc[c];
        if (x) {
            float xv = x[ob + col];
            float d = r - xv;
            local += d * d;
            recon_out[ob + col] = r;
            resid_out[ob + col] = xv - r;
        } else {
            float d = r - resid_in[ob + col];
            local += d * d;
        }
    }
    sred[tid] = local;
    __syncthreads();
    for (int s = 128; s > 0; s >>= 1) {
        if (tid < s) sred[tid] += sred[tid + s];
        __syncthreads();
    }
    if (tid == 0) part[tok] = sred[0];
}

// ------------------------------ dead mask -----------------------------------
__global__ void dead_kernel(const int* __restrict__ act,
                            const int* __restrict__ n_inactive,
                            int* __restrict__ dead, int D, int slot)
{
    int i = blockIdx.x * blockDim.x + threadIdx.x;
    if (i >= D) return;
    int d = (act[i] == 0) && (n_inactive[i] >= 2);
    dead[i] = d;
    if (d) atomicOr(&g_anydead[slot], 1);
}

// ------------------------------ finalize ------------------------------------
__global__ void finalize_kernel(float* __restrict__ outsc)
{
    __shared__ double sred[256];
    __shared__ double tot[4];
    int tid = threadIdx.x;
    for (int a = 0; a < 4; a++) {
        double loc = 0.0;
        for (int i = tid; i < NTOK; i += 256) loc += (double)g_part[a * NTOK + i];
        sred[tid] = loc;
        __syncthreads();
        for (int s = 128; s > 0; s >>= 1) {
            if (tid < s) sred[tid] += sred[tid + s];
            __syncthreads();
        }
        if (tid == 0) tot[a] = sred[0];
        __syncthreads();
    }
    if (tid == 0) {
        double denom = (double)NTOK * (double)DM;
        double l2 = tot[0] / denom;
        double aux = 0.0;
        if (g_anydead[0]) aux += tot[1] / denom;
        if (g_anydead[1]) aux += tot[2] / denom;
        if (g_anydead[2]) aux += tot[3] / denom;
        outsc[0] = (float)(l2 + 0.03125 * aux);
        outsc[1] = (float)l2;
        outsc[2] = (float)aux;
    }
}

// ------------------------------ launch --------------------------------------
extern "C" void kernel_launch(void* const* d_in, const int* in_sizes, int n_in,
                              void* d_out, int out_size)
{
    const float* x      = (const float*)d_in[0];
    const float* W_enc1 = (const float*)d_in[1];
    const float* b_enc1 = (const float*)d_in[2];
    const float* W_enc2 = (const float*)d_in[3];
    const float* b_enc2 = (const float*)d_in[4];
    const float* W_dec2 = (const float*)d_in[5];
    const float* b_dec2 = (const float*)d_in[6];
    const float* W_dec1 = (const float*)d_in[7];
    const float* b_dec1 = (const float*)d_in[8];
    const int* ni0 = (const int*)d_in[9];
    const int* ni1 = (const int*)d_in[10];
    const int* ni2 = (const int*)d_in[11];

    float* out = (float*)d_out;
    float* recon = out;
    float* scalars = out + (size_t)NTOK * DM;

    // device symbol addresses (usable directly in <<<>>> args via device code;
    // here we just need them as pointers for the generic kernels)
    float *pre0, *pre1, *pre2, *tfeat, *tmid, *resid;
    float *valA, *valB;
    int *idxA, *idxB, *cntA, *cntB;
    int *act0, *act1, *act2, *dead0, *dead1, *dead2;
    float* part;
    cudaGetSymbolAddress((void**)&pre0, g_pre0);
    cudaGetSymbolAddress((void**)&pre1, g_pre1);
    cudaGetSymbolAddress((void**)&pre2, g_pre2);
    cudaGetSymbolAddress((void**)&tfeat, g_tfeat);
    cudaGetSymbolAddress((void**)&tmid, g_tmid);
    cudaGetSymbolAddress((void**)&resid, g_resid);
    cudaGetSymbolAddress((void**)&valA, g_valA);
    cudaGetSymbolAddress((void**)&idxA, g_idxA);
    cudaGetSymbolAddress((void**)&cntA, g_cntA);
    cudaGetSymbolAddress((void**)&valB, g_valB);
    cudaGetSymbolAddress((void**)&idxB, g_idxB);
    cudaGetSymbolAddress((void**)&cntB, g_cntB);
    cudaGetSymbolAddress((void**)&act0, g_act0);
    cudaGetSymbolAddress((void**)&act1, g_act1);
    cudaGetSymbolAddress((void**)&act2, g_act2);
    cudaGetSymbolAddress((void**)&dead0, g_dead0);
    cudaGetSymbolAddress((void**)&dead1, g_dead1);
    cudaGetSymbolAddress((void**)&dead2, g_dead2);
    cudaGetSymbolAddress((void**)&part, g_part);

    cudaFuncSetAttribute(topk_kernel,
                         cudaFuncAttributeMaxDynamicSharedMemorySize,
                         DFEAT * sizeof(uint32_t));

    // 0. init flags
    init_kernel<<<(DMID + DFEAT + DMID + 3 + 255) / 256, 256>>>();

    // 1. pre0 = relu(x @ W_enc1 + b_enc1)
    sgemm_bias_relu<<<dim3(DMID / 128, NTOK / 128), 256>>>(
        x, W_enc1, b_enc1, pre0, NTOK, DMID, DM);

    // 2. mid0 = topk(pre0, 128) -> A
    topk_kernel<<<NTOK, 256, DMID * 4>>>(pre0, DMID, KMID, nullptr,
                                         idxA, valA, cntA, act0);
    // 3. pre1 = relu(mid0 @ W_enc2 + b_enc2)
    spgemm_kernel<8><<<dim3(NTOK, DFEAT / 2048), 256>>>(
        valA, idxA, cntA, W_enc2, b_enc2, pre1, DFEAT, 1);
    // 4. mid1 = topk(pre1, 64) -> B
    topk_kernel<<<NTOK, 256, DFEAT * 4>>>(pre1, DFEAT, KFEAT, nullptr,
                                          idxB, valB, cntB, act1);
    // 5. pre2 = relu(mid1 @ W_dec2 + b_dec2)
    spgemm_kernel<8><<<dim3(NTOK, DMID / 2048), 256>>>(
        valB, idxB, cntB, W_dec2, b_dec2, pre2, DMID, 1);
    // 6. mid2 = topk(pre2, 128) -> A
    topk_kernel<<<NTOK, 256, DMID * 4>>>(pre2, DMID, KMID, nullptr,
                                         idxA, valA, cntA, act2);
    // 7. recon = mid2 @ W_dec1 + b_dec1 ; residual, l2 partials
    spgemm_final_kernel<<<NTOK, 256>>>(valA, idxA, cntA, W_dec1, b_dec1,
                                       x, recon, resid, nullptr,
                                       part + 0 * NTOK);
    // 8. dead masks
    dead_kernel<<<DMID / 256, 256>>>(act0, ni0, dead0, DMID, 0);
    dead_kernel<<<DFEAT / 256, 256>>>(act1, ni1, dead1, DFEAT, 1);
    dead_kernel<<<DMID / 256, 256>>>(act2, ni2, dead2, DMID, 2);

    // ---- aux 0: dead-topk(pre0,256) -> enc2 -> topk64 -> dec2 -> topk128 -> dec1
    topk_kernel<<<NTOK, 256, DMID * 4>>>(pre0, DMID, KAUXM, dead0,
                                         idxB, valB, cntB, nullptr);
    spgemm_kernel<8><<<dim3(NTOK, DFEAT / 2048), 256>>>(
        valB, idxB, cntB, W_enc2, b_enc2, tfeat, DFEAT, 1);
    topk_kernel<<<NTOK, 256, DFEAT * 4>>>(tfeat, DFEAT, KFEAT, nullptr,
                                          idxA, valA, cntA, nullptr);
    spgemm_kernel<8><<<dim3(NTOK, DMID / 2048), 256>>>(
        valA, idxA, cntA, W_dec2, b_dec2, tmid, DMID, 1);
    topk_kernel<<<NTOK, 256, DMID * 4>>>(tmid, DMID, KMID, nullptr,
                                         idxB, valB, cntB, nullptr);
    spgemm_final_kernel<<<NTOK, 256>>>(valB, idxB, cntB, W_dec1, b_dec1,
                                       nullptr, nullptr, nullptr, resid,
                                       part + 1 * NTOK);

    // ---- aux 1: dead-topk(pre1,512) -> dec2 -> topk128 -> dec1
    topk_kernel<<<NTOK, 256, DFEAT * 4>>>(pre1, DFEAT, KAUXF, dead1,
                                          idxA, valA, cntA, nullptr);
    spgemm_kernel<8><<<dim3(NTOK, DMID / 2048), 256>>>(
        valA, idxA, cntA, W_dec2, b_dec2, tmid, DMID, 1);
    topk_kernel<<<NTOK, 256, DMID * 4>>>(tmid, DMID, KMID, nullptr,
                                         idxB, valB, cntB, nullptr);
    spgemm_final_kernel<<<NTOK, 256>>>(valB, idxB, cntB, W_dec1, b_dec1,
                                       nullptr, nullptr, nullptr, resid,
                                       part + 2 * NTOK);

    // ---- aux 2: dead-topk(pre2,256) -> dec1 (no relu, no topk)
    topk_kernel<<<NTOK, 256, DMID * 4>>>(pre2, DMID, KAUXM, dead2,
                                         idxA, valA, cntA, nullptr);
    spgemm_final_kernel<<<NTOK, 256>>>(valA, idxA, cntA, W_dec1, b_dec1,
                                       nullptr, nullptr, nullptr, resid,
                                       part + 3 * NTOK);

    // ---- scalars
    finalize_kernel<<<1, 256>>>(scalars);
}

// round 4
// speedup vs baseline: 1.2014x; 1.2014x over previous
#include <cuda_runtime.h>
#include <cuda_bf16.h>
#include <cstdint>

// ---------------------------------------------------------------------------
// DeepTopK sparse autoencoder forward + loss, fp32 throughout.
//   x:[2048,1024]  W_enc1:[1024,4096] W_enc2:[4096,16384]
//   W_dec2:[16384,4096] W_dec1:[4096,1024]
// Outputs: recon [2048*1024] then loss, l2_loss, aux_loss.
// ---------------------------------------------------------------------------

#define NTOK   2048
#define DM     1024
#define DMID   4096
#define DFEAT  16384
#define KMID   128
#define KFEAT  64
#define KAUXM  256
#define KAUXF  512
#define KCAP   512

// ------------------------- scratch (static device) -------------------------
__device__ float g_pre0[NTOK * DMID];
__device__ float g_pre1[(size_t)NTOK * DFEAT];
__device__ float g_pre2[NTOK * DMID];
__device__ float g_tfeat[(size_t)NTOK * DFEAT];
__device__ float g_tmid0[NTOK * DMID];
__device__ float g_tmid1[NTOK * DMID];
__device__ float g_resid[NTOK * DM];

// sparse buffers: A,B = main path; C,D = aux0; E,F = aux1; G = aux2
#define DECL_SP(nm) \
    __device__ float g_val##nm[NTOK * KCAP]; \
    __device__ int   g_idx##nm[NTOK * KCAP]; \
    __device__ int   g_cnt##nm[NTOK];
DECL_SP(A) DECL_SP(B) DECL_SP(C) DECL_SP(D) DECL_SP(E) DECL_SP(F) DECL_SP(G)

__device__ int g_act0[DMID];
__device__ int g_act1[DFEAT];
__device__ int g_act2[DMID];
__device__ int g_dead0[DMID];
__device__ int g_dead1[DFEAT];
__device__ int g_dead2[DMID];
__device__ int g_anydead[3];

__device__ float g_part[4 * NTOK];  // 0: l2, 1..3: aux terms

// ------------------------------ init ---------------------------------------
__global__ void init_kernel() {
    int i = blockIdx.x * blockDim.x + threadIdx.x;
    int total = DMID + DFEAT + DMID + 3;
    if (i >= total) return;
    if (i < DMID)               g_act0[i] = 0;
    else if (i < DMID + DFEAT)  g_act1[i - DMID] = 0;
    else if (i < DMID + DFEAT + DMID) g_act2[i - DMID - DFEAT] = 0;
    else                        g_anydead[i - DMID - DFEAT - DMID] = 0;
}

// ------------------------- dense SGEMM (layer 1) ----------------------------
// C[M,N] = relu(A[M,K] @ B[K,N] + bias[N]); M=2048,K=1024,N=4096
__global__ __launch_bounds__(256) void sgemm_bias_relu(
    const float* __restrict__ A, const float* __restrict__ B,
    const float* __restrict__ bias, float* __restrict__ C,
    int M, int N, int K)
{
    const int BM = 128, BN = 128, BK = 16, TM = 8, TN = 8;
    __shared__ float As[BK * BM];
    __shared__ float Bs[BK * BN];
    int tid = threadIdx.x;
    int tileN = blockIdx.x, tileM = blockIdx.y;
    const float* Ab = A + (size_t)tileM * BM * K;
    const float* Bb = B + (size_t)tileN * BN;
    float* Cb = C + (size_t)tileM * BM * N + (size_t)tileN * BN;

    int rowA = tid / 4;              // 0..63 (and +64)
    int colA = (tid % 4) * 4;        // 0,4,8,12
    int rowB = tid / 32;             // 0..7 (and +8)
    int colB = (tid % 32) * 4;
    int threadRow = tid / 16;
    int threadCol = tid % 16;

    float acc[TM][TN];
#pragma unroll
    for (int i = 0; i < TM; i++)
#pragma unroll
        for (int j = 0; j < TN; j++) acc[i][j] = 0.f;
    float regM[TM], regN[TN];

    for (int k0 = 0; k0 < K; k0 += BK) {
#pragma unroll
        for (int h = 0; h < 2; h++) {
            int r = rowA + h * 64;
            float4 a = *reinterpret_cast<const float4*>(Ab + (size_t)r * K + k0 + colA);
            As[(colA + 0) * BM + r] = a.x;
            As[(colA + 1) * BM + r] = a.y;
            As[(colA + 2) * BM + r] = a.z;
            As[(colA + 3) * BM + r] = a.w;
        }
#pragma unroll
        for (int h = 0; h < 2; h++) {
            int r = rowB + h * 8;
            *reinterpret_cast<float4*>(&Bs[r * BN + colB]) =
                *reinterpret_cast<const float4*>(Bb + (size_t)(k0 + r) * N + colB);
        }
        __syncthreads();
#pragma unroll
        for (int k = 0; k < BK; k++) {
#pragma unroll
            for (int i = 0; i < TM; i++) regM[i] = As[k * BM + threadRow * TM + i];
#pragma unroll
            for (int j = 0; j < TN; j++) regN[j] = Bs[k * BN + threadCol * TN + j];
#pragma unroll
            for (int i = 0; i < TM; i++)
#pragma unroll
                for (int j = 0; j < TN; j++)
                    acc[i][j] = fmaf(regM[i], regN[j], acc[i][j]);
        }
        __syncthreads();
    }
#pragma unroll
    for (int i = 0; i < TM; i++) {
        int row = threadRow * TM + i;
#pragma unroll
        for (int j = 0; j < TN; j++) {
            int col = threadCol * TN + j;
            float v = acc[i][j] + bias[tileN * BN + col];
            Cb[(size_t)row * N + col] = fmaxf(v, 0.f);
        }
    }
}

// ----------------------------- TopK (radix select) --------------------------
// One block (512 thr) per row. Keys: float bits | 0x80000000 (inputs >= 0);
// dead-mask mode maps live features to key 0 (acts as -inf, never emitted).
// Deterministic emission in index order (strict-greater, then ties).
__global__ __launch_bounds__(512) void topk_kernel(
    const float* __restrict__ in, int D, int k,
    const int* __restrict__ dead,
    int* __restrict__ out_idx, float* __restrict__ out_val,
    int* __restrict__ out_cnt, int* __restrict__ act)
{
    extern __shared__ uint32_t skey[];
    __shared__ unsigned int hist[256];
    __shared__ unsigned int sfx[256];
    __shared__ int sg[512], st[512];
    __shared__ uint32_t s_uT;
    __shared__ int s_remk, s_totg, s_tott;
    const int NT = 512;
    int tid = threadIdx.x;
    int lane = tid & 31;
    const float* row = in + (size_t)blockIdx.x * D;

    for (int i = tid; i < D; i += NT) {
        uint32_t u;
        if (dead && !dead[i]) u = 0u;
        else u = __float_as_uint(row[i]) | 0x80000000u;
        skey[i] = u;
    }
    __syncthreads();

    uint32_t prefix = 0, himask = 0;
    int remk = k;
    for (int pass = 0; pass < 4; ++pass) {
        int shift = 24 - 8 * pass;
        if (tid < 256) hist[tid] = 0u;
        __syncthreads();
        for (int i = tid; i < D; i += NT) {
            uint32_t u = skey[i];
            bool pred = ((u & himask) == prefix);
            unsigned am = __ballot_sync(0xffffffffu, pred);
            if (pred) {
                unsigned bin = (u >> shift) & 255u;
                unsigned m = __match_any_sync(am, bin);
                int leader = __ffs(m) - 1;
                if (lane == leader) atomicAdd(&hist[bin], __popc(m));
            }
        }
        __syncthreads();
        // inclusive suffix sum of hist -> sfx
        unsigned v0 = 0;
        if (tid < 256) v0 = hist[tid];
        sfx[tid < 256 ? tid : 0] = (tid < 256) ? v0 : sfx[0];  // write only tid<256
        __syncthreads();
        for (int off = 1; off < 256; off <<= 1) {
            unsigned v = 0;
            if (tid < 256) v = sfx[tid] + ((tid + off < 256) ? sfx[tid + off] : 0u);
            __syncthreads();
            if (tid < 256) sfx[tid] = v;
            __syncthreads();
        }
        if (tid < 256) {
            unsigned above = (tid == 255) ? 0u : sfx[tid + 1];
            if (sfx[tid] >= (unsigned)remk && above < (unsigned)remk) {
                s_uT = prefix | ((uint32_t)tid << shift);
                s_remk = remk - (int)above;
            }
        }
        __syncthreads();
        prefix = s_uT;
        remk = s_remk;
        himask |= (0xFFu << shift);
        __syncthreads();
    }
    uint32_t uT = prefix;

    // deterministic chunked emission (chunk order == index order)
    int C = D / NT;
    int base = tid * C;
    int gc = 0, tc = 0;
    for (int i = 0; i < C; i++) {
        uint32_t u = skey[base + i];
        if (u > uT) gc++;
        else if (u == uT && u != 0u) tc++;
    }
    sg[tid] = gc; st[tid] = tc;
    __syncthreads();
    // inclusive prefix scans over 512
    for (int off = 1; off < NT; off <<= 1) {
        int vg = sg[tid] + ((tid >= off) ? sg[tid - off] : 0);
        int vt = st[tid] + ((tid >= off) ? st[tid - off] : 0);
        __syncthreads();
        sg[tid] = vg; st[tid] = vt;
        __syncthreads();
    }
    if (tid == NT - 1) { s_totg = sg[tid]; s_tott = st[tid]; }
    __syncthreads();
    int gpos = sg[tid] - gc;   // exclusive
    int tpos = st[tid] - tc;
    int Kg = s_totg;
    size_t ob = (size_t)blockIdx.x * KCAP;
    for (int i = 0; i < C; i++) {
        uint32_t u = skey[base + i];
        if (u > uT) {
            float v = __uint_as_float(u & 0x7FFFFFFFu);
            out_idx[ob + gpos] = base + i;
            out_val[ob + gpos] = v;
            if (act && v > 0.f) act[base + i] = 1;
            gpos++;
        } else if (u == uT && u != 0u) {
            if (tpos < remk) {
                float v = __uint_as_float(u & 0x7FFFFFFFu);
                int s = Kg + tpos;
                out_idx[ob + s] = base + i;
                out_val[ob + s] = v;
                if (act && v > 0.f) act[base + i] = 1;
            }
            tpos++;
        }
    }
    if (tid == 0) {
        int ties = s_tott < remk ? s_tott : remk;
        out_cnt[blockIdx.x] = Kg + ties;
    }
}

// -------------------------- gather-SpMM (float4) ----------------------------
// out[tok,:] = (relu?)(sum_j val_j * W[idx_j,:] + bias)
// grid = (NTOK, Dout/(1024*CPT4)); token fastest => W chunk stays in L2.
template <int CPT4>
__global__ __launch_bounds__(256) void spgemm_kernel(
    const float* __restrict__ vals, const int* __restrict__ idxs,
    const int* __restrict__ cnts,
    const float* __restrict__ W, const float* __restrict__ bias,
    float* __restrict__ out, int Dout, int do_relu)
{
    __shared__ float sv[KCAP];
    __shared__ int si[KCAP];
    int tok = blockIdx.x, tid = threadIdx.x;
    int Keff = cnts[tok];
    for (int i = tid; i < Keff; i += 256) {
        sv[i] = vals[(size_t)tok * KCAP + i];
        si[i] = idxs[(size_t)tok * KCAP + i];
    }
    __syncthreads();
    int colBase = blockIdx.y * (1024 * CPT4) + tid * 4;
    float4 acc[CPT4];
#pragma unroll
    for (int c = 0; c < CPT4; c++)
        acc[c] = __ldg(reinterpret_cast<const float4*>(bias + colBase + c * 1024));
#pragma unroll 4
    for (int j = 0; j < Keff; j++) {
        float v = sv[j];
        const float* w = W + (size_t)si[j] * Dout + colBase;
#pragma unroll
        for (int c = 0; c < CPT4; c++) {
            float4 wv = __ldg(reinterpret_cast<const float4*>(w + c * 1024));
            acc[c].x = fmaf(v, wv.x, acc[c].x);
            acc[c].y = fmaf(v, wv.y, acc[c].y);
            acc[c].z = fmaf(v, wv.z, acc[c].z);
            acc[c].w = fmaf(v, wv.w, acc[c].w);
        }
    }
    float* o = out + (size_t)tok * Dout + colBase;
#pragma unroll
    for (int c = 0; c < CPT4; c++) {
        float4 r = acc[c];
        if (do_relu) {
            r.x = fmaxf(r.x, 0.f); r.y = fmaxf(r.y, 0.f);
            r.z = fmaxf(r.z, 0.f); r.w = fmaxf(r.w, 0.f);
        }
        *reinterpret_cast<float4*>(o + c * 1024) = r;
    }
}

// ----------------- final-layer SpMM + squared-error partials ----------------
// Dout = 1024. recon mode (x != nullptr): writes recon + residual + l2 partial.
// aux mode: partial sum of (h - resid_in)^2 only.
__global__ __launch_bounds__(256) void spgemm_final_kernel(
    const float* __restrict__ vals, const int* __restrict__ idxs,
    const int* __restrict__ cnts,
    const float* __restrict__ W, const float* __restrict__ bias,
    const float* __restrict__ x, float* __restrict__ recon_out,
    float* __restrict__ resid_out, const float* __restrict__ resid_in,
    float* __restrict__ part)
{
    __shared__ float sv[KCAP];
    __shared__ int si[KCAP];
    __shared__ float sred[256];
    int tok = blockIdx.x, tid = threadIdx.x;
    int Keff = cnts[tok];
    for (int i = tid; i < Keff; i += 256) {
        sv[i] = vals[(size_t)tok * KCAP + i];
        si[i] = idxs[(size_t)tok * KCAP + i];
    }
    __syncthreads();
    int col = tid * 4;
    float4 acc = __ldg(reinterpret_cast<const float4*>(bias + col));
#pragma unroll 4
    for (int j = 0; j < Keff; j++) {
        float v = sv[j];
        float4 wv = __ldg(reinterpret_cast<const float4*>(W + (size_t)si[j] * DM + col));
        acc.x = fmaf(v, wv.x, acc.x);
        acc.y = fmaf(v, wv.y, acc.y);
        acc.z = fmaf(v, wv.z, acc.z);
        acc.w = fmaf(v, wv.w, acc.w);
    }
    size_t ob = (size_t)tok * DM;
    float local;
    if (x) {
        float4 xv = *reinterpret_cast<const float4*>(x + ob + col);
        float4 d = make_float4(acc.x - xv.x, acc.y - xv.y, acc.z - xv.z, acc.w - xv.w);
        local = d.x * d.x + d.y * d.y + d.z * d.z + d.w * d.w;
        *reinterpret_cast<float4*>(recon_out + ob + col) = acc;
        *reinterpret_cast<float4*>(resid_out + ob + col) =
            make_float4(-d.x, -d.y, -d.z, -d.w);
    } else {
        float4 rv = *reinterpret_cast<const float4*>(resid_in + ob + col);
        float4 d = make_float4(acc.x - rv.x, acc.y - rv.y, acc.z - rv.z, acc.w - rv.w);
        local = d.x * d.x + d.y * d.y + d.z * d.z + d.w * d.w;
    }
    sred[tid] = local;
    __syncthreads();
    for (int s = 128; s > 0; s >>= 1) {
        if (tid < s) sred[tid] += sred[tid + s];
        __syncthreads();
    }
    if (tid == 0) part[tok] = sred[0];
}

// ------------------------------ dead mask -----------------------------------
__global__ void dead_kernel(const int* __restrict__ act,
                            const int* __restrict__ n_inactive,
                            int* __restrict__ dead, int D, int slot)
{
    int i = blockIdx.x * blockDim.x + threadIdx.x;
    if (i >= D) return;
    int d = (act[i] == 0) && (n_inactive[i] >= 2);
    dead[i] = d;
    if (d) atomicOr(&g_anydead[slot], 1);
}

// ------------------------------ finalize ------------------------------------
__global__ void finalize_kernel(float* __restrict__ outsc)
{
    __shared__ double sred[256];
    __shared__ double tot[4];
    int tid = threadIdx.x;
    for (int a = 0; a < 4; a++) {
        double loc = 0.0;
        for (int i = tid; i < NTOK; i += 256) loc += (double)g_part[a * NTOK + i];
        sred[tid] = loc;
        __syncthreads();
        for (int s = 128; s > 0; s >>= 1) {
            if (tid < s) sred[tid] += sred[tid + s];
            __syncthreads();
        }
        if (tid == 0) tot[a] = sred[0];
        __syncthreads();
    }
    if (tid == 0) {
        double denom = (double)NTOK * (double)DM;
        double l2 = tot[0] / denom;
        double aux = 0.0;
        if (g_anydead[0]) aux += tot[1] / denom;
        if (g_anydead[1]) aux += tot[2] / denom;
        if (g_anydead[2]) aux += tot[3] / denom;
        outsc[0] = (float)(l2 + 0.03125 * aux);
        outsc[1] = (float)l2;
        outsc[2] = (float)aux;
    }
}

// ------------------------------ launch --------------------------------------
extern "C" void kernel_launch(void* const* d_in, const int* in_sizes, int n_in,
                              void* d_out, int out_size)
{
    const float* x      = (const float*)d_in[0];
    const float* W_enc1 = (const float*)d_in[1];
    const float* b_enc1 = (const float*)d_in[2];
    const float* W_enc2 = (const float*)d_in[3];
    const float* b_enc2 = (const float*)d_in[4];
    const float* W_dec2 = (const float*)d_in[5];
    const float* b_dec2 = (const float*)d_in[6];
    const float* W_dec1 = (const float*)d_in[7];
    const float* b_dec1 = (const float*)d_in[8];
    const int* ni0 = (const int*)d_in[9];
    const int* ni1 = (const int*)d_in[10];
    const int* ni2 = (const int*)d_in[11];

    float* out = (float*)d_out;
    float* recon = out;
    float* scalars = out + (size_t)NTOK * DM;

    float *pre0, *pre1, *pre2, *tfeat, *tmid0, *tmid1, *resid, *part;
    cudaGetSymbolAddress((void**)&pre0, g_pre0);
    cudaGetSymbolAddress((void**)&pre1, g_pre1);
    cudaGetSymbolAddress((void**)&pre2, g_pre2);
    cudaGetSymbolAddress((void**)&tfeat, g_tfeat);
    cudaGetSymbolAddress((void**)&tmid0, g_tmid0);
    cudaGetSymbolAddress((void**)&tmid1, g_tmid1);
    cudaGetSymbolAddress((void**)&resid, g_resid);
    cudaGetSymbolAddress((void**)&part, g_part);

#define GETSP(nm) \
    float* val##nm; int *idx##nm, *cnt##nm; \
    cudaGetSymbolAddress((void**)&val##nm, g_val##nm); \
    cudaGetSymbolAddress((void**)&idx##nm, g_idx##nm); \
    cudaGetSymbolAddress((void**)&cnt##nm, g_cnt##nm);
    GETSP(A) GETSP(B) GETSP(C) GETSP(D) GETSP(E) GETSP(F) GETSP(G)

    int *act0, *act1, *act2, *dead0, *dead1, *dead2;
    cudaGetSymbolAddress((void**)&act0, g_act0);
    cudaGetSymbolAddress((void**)&act1, g_act1);
    cudaGetSymbolAddress((void**)&act2, g_act2);
    cudaGetSymbolAddress((void**)&dead0, g_dead0);
    cudaGetSymbolAddress((void**)&dead1, g_dead1);
    cudaGetSymbolAddress((void**)&dead2, g_dead2);

    cudaFuncSetAttribute(topk_kernel,
                         cudaFuncAttributeMaxDynamicSharedMemorySize,
                         DFEAT * sizeof(uint32_t));

    // side streams + events (created once, outside capture: the harness's
    // correctness call precedes graph capture)
    static cudaStream_t s1 = nullptr, s2 = nullptr, s3 = nullptr;
    static cudaEvent_t evFork = nullptr, ev1 = nullptr, ev2 = nullptr, ev3 = nullptr;
    if (!s1) {
        cudaStreamCreateWithFlags(&s1, cudaStreamNonBlocking);
        cudaStreamCreateWithFlags(&s2, cudaStreamNonBlocking);
        cudaStreamCreateWithFlags(&s3, cudaStreamNonBlocking);
        cudaEventCreateWithFlags(&evFork, cudaEventDisableTiming);
        cudaEventCreateWithFlags(&ev1, cudaEventDisableTiming);
        cudaEventCreateWithFlags(&ev2, cudaEventDisableTiming);
        cudaEventCreateWithFlags(&ev3, cudaEventDisableTiming);
    }

    // ---------------- main path (default stream) ----------------
    init_kernel<<<(DMID + DFEAT + DMID + 3 + 255) / 256, 256>>>();

    sgemm_bias_relu<<<dim3(DMID / 128, NTOK / 128), 256>>>(
        x, W_enc1, b_enc1, pre0, NTOK, DMID, DM);

    topk_kernel<<<NTOK, 512, DMID * 4>>>(pre0, DMID, KMID, nullptr,
                                         idxA, valA, cntA, act0);
    spgemm_kernel<2><<<dim3(NTOK, DFEAT / 2048), 256>>>(
        valA, idxA, cntA, W_enc2, b_enc2, pre1, DFEAT, 1);
    topk_kernel<<<NTOK, 512, DFEAT * 4>>>(pre1, DFEAT, KFEAT, nullptr,
                                          idxB, valB, cntB, act1);
    spgemm_kernel<2><<<dim3(NTOK, DMID / 2048), 256>>>(
        valB, idxB, cntB, W_dec2, b_dec2, pre2, DMID, 1);
    topk_kernel<<<NTOK, 512, DMID * 4>>>(pre2, DMID, KMID, nullptr,
                                         idxA, valA, cntA, act2);
    spgemm_final_kernel<<<NTOK, 256>>>(valA, idxA, cntA, W_dec1, b_dec1,
                                       x, recon, resid, nullptr,
                                       part + 0 * NTOK);
    dead_kernel<<<DMID / 256, 256>>>(act0, ni0, dead0, DMID, 0);
    dead_kernel<<<DFEAT / 256, 256>>>(act1, ni1, dead1, DFEAT, 1);
    dead_kernel<<<DMID / 256, 256>>>(act2, ni2, dead2, DMID, 2);

    // ---------------- fork: three independent aux chains ----------------
    cudaEventRecord(evFork, 0);
    cudaStreamWaitEvent(s1, evFork, 0);
    cudaStreamWaitEvent(s2, evFork, 0);
    cudaStreamWaitEvent(s3, evFork, 0);

    // aux 0: dead-topk(pre0,256) -> enc2 -> topk64 -> dec2 -> topk128 -> dec1
    topk_kernel<<<NTOK, 512, DMID * 4, s1>>>(pre0, DMID, KAUXM, dead0,
                                             idxC, valC, cntC, nullptr);
    spgemm_kernel<2><<<dim3(NTOK, DFEAT / 2048), 256, 0, s1>>>(
        valC, idxC, cntC, W_enc2, b_enc2, tfeat, DFEAT, 1);
    topk_kernel<<<NTOK, 512, DFEAT * 4, s1>>>(tfeat, DFEAT, KFEAT, nullptr,
                                              idxD, valD, cntD, nullptr);
    spgemm_kernel<2><<<dim3(NTOK, DMID / 2048), 256, 0, s1>>>(
        valD, idxD, cntD, W_dec2, b_dec2, tmid0, DMID, 1);
    topk_kernel<<<NTOK, 512, DMID * 4, s1>>>(tmid0, DMID, KMID, nullptr,
                                             idxC, valC, cntC, nullptr);
    spgemm_final_kernel<<<NTOK, 256, 0, s1>>>(valC, idxC, cntC, W_dec1, b_dec1,
                                              nullptr, nullptr, nullptr, resid,
                                              part + 1 * NTOK);

    // aux 1: dead-topk(pre1,512) -> dec2 -> topk128 -> dec1
    topk_kernel<<<NTOK, 512, DFEAT * 4, s2>>>(pre1, DFEAT, KAUXF, dead1,
                                              idxE, valE, cntE, nullptr);
    spgemm_kernel<2><<<dim3(NTOK, DMID / 2048), 256, 0, s2>>>(
        valE, idxE, cntE, W_dec2, b_dec2, tmid1, DMID, 1);
    topk_kernel<<<NTOK, 512, DMID * 4, s2>>>(tmid1, DMID, KMID, nullptr,
                                             idxF, valF, cntF, nullptr);
    spgemm_final_kernel<<<NTOK, 256, 0, s2>>>(valF, idxF, cntF, W_dec1, b_dec1,
                                              nullptr, nullptr, nullptr, resid,
                                              part + 2 * NTOK);

    // aux 2: dead-topk(pre2,256) -> dec1
    topk_kernel<<<NTOK, 512, DMID * 4, s3>>>(pre2, DMID, KAUXM, dead2,
                                             idxG, valG, cntG, nullptr);
    spgemm_final_kernel<<<NTOK, 256, 0, s3>>>(valG, idxG, cntG, W_dec1, b_dec1,
                                              nullptr, nullptr, nullptr, resid,
                                              part + 3 * NTOK);

    // ---------------- join + finalize ----------------
    cudaEventRecord(ev1, s1);
    cudaEventRecord(ev2, s2);
    cudaEventRecord(ev3, s3);
    cudaStreamWaitEvent(0, ev1, 0);
    cudaStreamWaitEvent(0, ev2, 0);
    cudaStreamWaitEvent(0, ev3, 0);
    finalize_kernel<<<1, 256>>>(scalars);
}